// round 12
// baseline (speedup 1.0000x reference)
#include <cuda_runtime.h>
#include <cuda_fp16.h>
#include <cuda_bf16.h>

// Shapes (compile-time)
#define T_    512
#define C_    768
#define KVC_  384
#define NH_   12
#define NKV_  6
#define HD_   64
#define HALF_ 32
#define NSPLIT 3
#define NQKV  1536        // 768 q + 384 k + 384 v output columns
#define QKSPLIT 4         // QKV GEMM split-K
#define PJSPLIT 4         // proj GEMM split-K

// ---------------- scratch (device globals: no allocs allowed) ----------------
__device__ __half g_xh[T_ * C_];            // x in fp16
__device__ __half g_Wqkvt[NQKV * C_];       // [n][k] fp16
__device__ __half g_Wpt[C_ * C_];           // Wproj^T [n][k] fp16
__device__ float  g_qkvp[QKSPLIT][T_ * NQKV];  // QKV split-K partials
__device__ float  g_Q[NH_ * T_ * HD_];      // head-major, rope+rmsnormed
__device__ float  g_K[NKV_ * T_ * HD_];
__device__ float  g_V[NKV_ * T_ * HD_];
__device__ __half g_Yh[T_ * C_];            // attention output fp16 (t, h*64+d)
// split-KV attention partials
__device__ float g_Pa[NSPLIT][NH_ * T_ * HD_];
__device__ float g_Pm[NSPLIT][NH_ * T_];
__device__ float g_Pl[NSPLIT][NH_ * T_];

// ---------------- kernel 0a: convert x to fp16 + zero proj target ------------
__global__ void xconv_kernel(const float* __restrict__ x, float* __restrict__ out) {
    int i = blockIdx.x * blockDim.x + threadIdx.x;
    if (i < T_ * C_) { g_xh[i] = __float2half(x[i]); out[i] = 0.0f; }
}

// ---------------- kernel 0b: transpose+convert weights to [n][k] fp16 --------
__global__ void wtrans_kernel(const float* __restrict__ Wq,
                              const float* __restrict__ Wk,
                              const float* __restrict__ Wv,
                              const float* __restrict__ Wp) {
    __shared__ float tile[32][33];
    const float* W; __half* dst; int ncols;
    switch (blockIdx.z) {
        case 0: W = Wq; ncols = C_;   dst = g_Wqkvt;                 break;
        case 1: W = Wk; ncols = KVC_; dst = g_Wqkvt + 768 * C_;      break;
        case 2: W = Wv; ncols = KVC_; dst = g_Wqkvt + 1152 * C_;     break;
        default: W = Wp; ncols = C_;  dst = g_Wpt;                   break;
    }
    int k0 = blockIdx.x * 32;
    int n0 = blockIdx.y * 32;
    if (n0 >= ncols) return;
    int tx = threadIdx.x, ty = threadIdx.y;
#pragma unroll
    for (int i = 0; i < 4; i++) {
        int r = ty + i * 8;
        tile[r][tx] = W[(size_t)(k0 + r) * ncols + n0 + tx];
    }
    __syncthreads();
#pragma unroll
    for (int i = 0; i < 4; i++) {
        int r = ty + i * 8;
        dst[(size_t)(n0 + r) * C_ + k0 + tx] = __float2half(tile[tx][r]);
    }
}

// ---------------- fp16 tensor-core GEMM tile (3-stage pipeline) --------------
// C[M,N] = A[M,K](fp16,row) @ Bt[N,K](fp16,row)^T, fp32 accum.
// BM=BN=64, BK=32, 128 threads (4 warps 2x2, warp tile 32x32).
#define HBM 64
#define HBN 64
#define HBK 32
#define HSA 40
#define NST 3

__device__ __forceinline__ void mma16816(float* d, const unsigned* a, const unsigned* b) {
    asm volatile(
        "mma.sync.aligned.m16n8k16.row.col.f32.f16.f16.f32 "
        "{%0,%1,%2,%3}, {%4,%5,%6,%7}, {%8,%9}, {%0,%1,%2,%3};"
        : "+f"(d[0]), "+f"(d[1]), "+f"(d[2]), "+f"(d[3])
        : "r"(a[0]), "r"(a[1]), "r"(a[2]), "r"(a[3]), "r"(b[0]), "r"(b[1]));
}

__device__ __forceinline__ void ldsm4(unsigned* d, const __half* p) {
    unsigned addr = (unsigned)__cvta_generic_to_shared(p);
    asm volatile("ldmatrix.sync.aligned.m8n8.x4.shared.b16 {%0,%1,%2,%3}, [%4];"
                 : "=r"(d[0]), "=r"(d[1]), "=r"(d[2]), "=r"(d[3]) : "r"(addr));
}

__device__ __forceinline__ void cpasync16(const __half* s, const __half* g) {
    unsigned addr = (unsigned)__cvta_generic_to_shared(s);
    asm volatile("cp.async.cg.shared.global [%0], [%1], 16;" :: "r"(addr), "l"(g));
}

template<bool ATOMIC>
__device__ __forceinline__ void hgemm_tile(
        const __half* __restrict__ A, int lda,
        const __half* __restrict__ Bt, int ldb,
        float* __restrict__ C, int ldc,
        int m0, int n0, int k_begin, int k_end) {
    __shared__ __align__(16) __half As[NST][HBM][HSA];
    __shared__ __align__(16) __half Bs[NST][HBN][HSA];

    const int tid = threadIdx.x;
    const int w = tid >> 5, lane = tid & 31;
    const int wm = (w >> 1) * 32, wn = (w & 1) * 32;
    const int g = lane >> 2, t = lane & 3;

    float acc[2][4][4] = {};
    const int nsteps = (k_end - k_begin) / HBK;   // >= 2 for all call sites

    auto load_stage = [&](int st, int k0) {
#pragma unroll
        for (int i = 0; i < 2; i++) {
            int c = tid + i * 128;
            int r = c >> 2, col = (c & 3) * 8;
            cpasync16(&As[st][r][col], A + (size_t)(m0 + r) * lda + k0 + col);
            cpasync16(&Bs[st][r][col], Bt + (size_t)(n0 + r) * ldb + k0 + col);
        }
    };

    load_stage(0, k_begin);
    asm volatile("cp.async.commit_group;");
    load_stage(1, k_begin + HBK);
    asm volatile("cp.async.commit_group;");

    for (int s = 0; s < nsteps; s++) {
        int st = s % NST;
        if (s + 1 < nsteps) asm volatile("cp.async.wait_group 1;");
        else                asm volatile("cp.async.wait_group 0;");
        __syncthreads();
        if (s + 2 < nsteps) {
            load_stage((s + 2) % NST, k_begin + (s + 2) * HBK);
            asm volatile("cp.async.commit_group;");
        }
#pragma unroll
        for (int ks = 0; ks < 2; ks++) {
            unsigned a[2][4], b[2][4];
#pragma unroll
            for (int mt = 0; mt < 2; mt++)
                ldsm4(a[mt], &As[st][wm + mt * 16 + (lane & 15)][ks * 16 + (lane >> 4) * 8]);
#pragma unroll
            for (int p = 0; p < 2; p++)
                ldsm4(b[p], &Bs[st][wn + p * 16 + ((lane >> 4) & 1) * 8 + (lane & 7)]
                               [ks * 16 + ((lane >> 3) & 1) * 8]);
#pragma unroll
            for (int mt = 0; mt < 2; mt++)
#pragma unroll
                for (int p = 0; p < 2; p++) {
                    mma16816(acc[mt][2 * p],     a[mt], &b[p][0]);
                    mma16816(acc[mt][2 * p + 1], a[mt], &b[p][2]);
                }
        }
    }

#pragma unroll
    for (int mt = 0; mt < 2; mt++) {
#pragma unroll
        for (int nt = 0; nt < 4; nt++) {
            int row0 = m0 + wm + mt * 16 + g;
            int col  = n0 + wn + nt * 8 + 2 * t;
            if (ATOMIC) {
                atomicAdd(&C[(size_t)row0 * ldc + col],     acc[mt][nt][0]);
                atomicAdd(&C[(size_t)row0 * ldc + col + 1], acc[mt][nt][1]);
                atomicAdd(&C[(size_t)(row0 + 8) * ldc + col],     acc[mt][nt][2]);
                atomicAdd(&C[(size_t)(row0 + 8) * ldc + col + 1], acc[mt][nt][3]);
            } else {
                *(float2*)&C[(size_t)row0 * ldc + col] = make_float2(acc[mt][nt][0], acc[mt][nt][1]);
                *(float2*)&C[(size_t)(row0 + 8) * ldc + col] = make_float2(acc[mt][nt][2], acc[mt][nt][3]);
            }
        }
    }
}

// ---------------- kernel 1: QKV GEMM (split-K=4, partial buffers) ------------
__global__ __launch_bounds__(128) void qkv_hgemm_kernel() {
    int sp = blockIdx.z;
    int kb = sp * (C_ / QKSPLIT);               // 192 per split, 6 k-steps
    hgemm_tile<false>(g_xh, C_, g_Wqkvt, C_, g_qkvp[sp], NQKV,
                      blockIdx.y * HBM, blockIdx.x * HBN, kb, kb + C_ / QKSPLIT);
}

// ---------------- kernel 2: RoPE + RMSNorm + head transpose + split-K sum ----
__global__ void rope_norm_kernel(const float* __restrict__ cosp,
                                 const float* __restrict__ sinp) {
    int t = blockIdx.x;
    int warp = threadIdx.x >> 5;
    int lane = threadIdx.x & 31;
    float c = cosp[t * HALF_ + lane];
    float s = sinp[t * HALF_ + lane];

    for (int task = warp; task < 24; task += 8) {
        int col;                            // column in the 1536-wide QKV output
        if (task < NH_)             col = task * HD_;
        else if (task < NH_ + NKV_) col = 768 + (task - NH_) * HD_;
        else                        col = 1152 + (task - NH_ - NKV_) * HD_;
        size_t off = (size_t)t * NQKV + col;
        float x1 = 0.0f, x2 = 0.0f;
#pragma unroll
        for (int sp = 0; sp < QKSPLIT; sp++) {
            x1 += g_qkvp[sp][off + lane];
            x2 += g_qkvp[sp][off + lane + HALF_];
        }

        if (task < NH_) {                   // Q head
            int h = task;
            float o1 = x1 * c - x2 * s;
            float o2 = x2 * c + x1 * s;
            float ss = o1 * o1 + o2 * o2;
#pragma unroll
            for (int o = 16; o; o >>= 1) ss += __shfl_xor_sync(0xffffffffu, ss, o);
            float r = rsqrtf(ss * (1.0f / HD_) + 1e-6f);
            float* dst = g_Q + ((size_t)h * T_ + t) * HD_;
            dst[lane] = o1 * r;
            dst[lane + HALF_] = o2 * r;
        } else if (task < NH_ + NKV_) {     // K head
            int h = task - NH_;
            float o1 = x1 * c - x2 * s;
            float o2 = x2 * c + x1 * s;
            float ss = o1 * o1 + o2 * o2;
#pragma unroll
            for (int o = 16; o; o >>= 1) ss += __shfl_xor_sync(0xffffffffu, ss, o);
            float r = rsqrtf(ss * (1.0f / HD_) + 1e-6f);
            float* dst = g_K + ((size_t)h * T_ + t) * HD_;
            dst[lane] = o1 * r;
            dst[lane + HALF_] = o2 * r;
        } else {                            // V: plain head-major copy
            int h = task - NH_ - NKV_;
            float* dst = g_V + ((size_t)h * T_ + t) * HD_;
            dst[lane] = x1;
            dst[lane + HALF_] = x2;
        }
    }
}

// ---------------- kernel 3: split-KV block-tiled tropical flash attention ----
// 3 blocks/SM target (regs forced <= 85).
__global__ __launch_bounds__(256, 3) void attn_kernel() {
    __shared__ float  Qs[32][68];          // [row][d] padded
    __shared__ float4 KT4[16][33];         // [d-group][key] padded
    __shared__ float2 VsT[32][34];         // [dim-pair][key]: VsT[p][j] = (V[j][2p], V[j][2p+1])
    __shared__ float4 ws4[8][4][8];        // [warp][r][key-group] staged weights

    int h = blockIdx.y;
    int split = blockIdx.z;
    int kv = h >> 1;                       // n_rep = 2
    int tid = threadIdx.x;
    int warp = tid >> 5, lane = tid & 31;
    const float* Kb = g_K + (size_t)kv * T_ * HD_;
    const float* Vb = g_V + (size_t)kv * T_ * HD_;

    for (int pass = 0; pass < 2; pass++) {
        int qt = pass ? (15 - blockIdx.x) : blockIdx.x;
        int qbase = qt * 32;
        __syncthreads();                   // protect previous pass's shared reads
#pragma unroll
        for (int i = 0; i < 2; i++) {      // load 32x64 Q tile
            int f = tid + i * 256;
            int r = f >> 4, dg = f & 15;
            float4 qv = *(const float4*)(g_Q + ((size_t)h * T_ + qbase + r) * HD_ + dg * 4);
            *(float4*)&Qs[r][dg * 4] = qv;
        }

        float m[4], l[4], a0[4], a1[4], s[4];
#pragma unroll
        for (int r = 0; r < 4; r++) { m[r] = -1e30f; l[r] = 0.0f; a0[r] = 0.0f; a1[r] = 0.0f; }
        int qi0 = qbase + warp * 4;        // warp's first q row

        for (int j0 = split * 32; j0 < qbase + 32; j0 += NSPLIT * 32) {
            __syncthreads();               // prior tile consumed / Qs stores visible
#pragma unroll
            for (int i = 0; i < 2; i++) {  // load K (transposed) + V (pair-major)
                int f = tid + i * 256;
                int j = f >> 4, dg = f & 15;
                KT4[dg][j] = *(const float4*)(Kb + (size_t)(j0 + j) * HD_ + dg * 4);
                float4 vv = *(const float4*)(Vb + (size_t)(j0 + j) * HD_ + dg * 4);
                VsT[dg * 2 + 0][j] = make_float2(vv.x, vv.y);
                VsT[dg * 2 + 1][j] = make_float2(vv.z, vv.w);
            }
            __syncthreads();
            if (j0 > qi0 + 3) continue;    // tile fully masked for this warp

            // --- scores: s[r] = max_d(q[r][d] + k[lane][d]) ---
#pragma unroll
            for (int r = 0; r < 4; r++) s[r] = -1e30f;
#pragma unroll
            for (int dg = 0; dg < 16; dg++) {
                float4 k4 = KT4[dg][lane];
#pragma unroll
                for (int r = 0; r < 4; r++) {
                    float4 q4 = *(const float4*)&Qs[warp * 4 + r][dg * 4];
                    float t0 = fmaxf(q4.x + k4.x, q4.y + k4.y);
                    float t1 = fmaxf(q4.z + k4.z, q4.w + k4.w);
                    s[r] = fmaxf(s[r], fmaxf(t0, t1));
                }
            }
            // --- online softmax bookkeeping + stage weights (lane = key) ---
#pragma unroll
            for (int r = 0; r < 4; r++) {
                int qi = qi0 + r;
                if (j0 + lane > qi) s[r] = -1e30f;   // causal mask
                float tm = s[r];
#pragma unroll
                for (int o = 16; o; o >>= 1) tm = fmaxf(tm, __shfl_xor_sync(0xffffffffu, tm, o));
                float mn = fmaxf(m[r], tm);
                float corr = __expf(m[r] - mn);      // exp(-1e30) underflows to 0
                float w = __expf(s[r] - mn);
                m[r] = mn;
                l[r] = l[r] * corr + w;              // per-lane partial denom
                a0[r] *= corr; a1[r] *= corr;        // corr is lane-uniform
                ((float*)&ws4[warp][r][0])[lane] = w;
            }
            __syncwarp();
            // --- PV: lane = dim pair (2*lane, 2*lane+1), float4 over keys ---
#pragma unroll
            for (int r = 0; r < 4; r++) {
                float acc0 = a0[r], acc1 = a1[r];
#pragma unroll
                for (int jb = 0; jb < 8; jb++) {
                    float4 w4 = ws4[warp][r][jb];                        // broadcast
                    float4 vA = *(const float4*)&VsT[lane][jb * 4];
                    float4 vB = *(const float4*)&VsT[lane][jb * 4 + 2];
                    acc0 += w4.x * vA.x; acc1 += w4.x * vA.y;
                    acc0 += w4.y * vA.z; acc1 += w4.y * vA.w;
                    acc0 += w4.z * vB.x; acc1 += w4.z * vB.y;
                    acc0 += w4.w * vB.z; acc1 += w4.w * vB.w;
                }
                a0[r] = acc0; a1[r] = acc1;
            }
        }
        // --- finalize: reduce l across lanes, write split partials ---
#pragma unroll
        for (int r = 0; r < 4; r++) {
            float ls = l[r];
#pragma unroll
            for (int o = 16; o; o >>= 1) ls += __shfl_xor_sync(0xffffffffu, ls, o);
            int idx = h * T_ + qi0 + r;
            float* Pa = &g_Pa[split][(size_t)idx * HD_];
            Pa[2 * lane]     = a0[r];
            Pa[2 * lane + 1] = a1[r];
            if (lane == 0) { g_Pm[split][idx] = m[r]; g_Pl[split][idx] = ls; }
        }
    }
}

// ---------------- kernel 3b: merge KV-split partials, emit fp16 Y ------------
__global__ void attn_merge_kernel() {
    int gw = (blockIdx.x * blockDim.x + threadIdx.x) >> 5;
    int lane = threadIdx.x & 31;
    if (gw >= NH_ * T_) return;
    int h = gw / T_, qi = gw % T_;
    float mn = -1e30f;
#pragma unroll
    for (int sp = 0; sp < NSPLIT; sp++) mn = fmaxf(mn, g_Pm[sp][gw]);
    float wv[NSPLIT], l = 0.0f;
#pragma unroll
    for (int sp = 0; sp < NSPLIT; sp++) {
        wv[sp] = __expf(g_Pm[sp][gw] - mn);
        l += g_Pl[sp][gw] * wv[sp];
    }
    float inv = 1.0f / l;
    float y0 = 0.0f, y1 = 0.0f;
#pragma unroll
    for (int sp = 0; sp < NSPLIT; sp++) {
        const float* A = &g_Pa[sp][(size_t)gw * HD_];
        y0 += A[lane] * wv[sp];
        y1 += A[lane + HALF_] * wv[sp];
    }
    __half* Yp = g_Yh + (size_t)qi * C_ + h * HD_;
    Yp[lane] = __float2half(y0 * inv);
    Yp[lane + HALF_] = __float2half(y1 * inv);
}

// ---------------- kernel 4: output projection (split-K=4, atomics) -----------
__global__ __launch_bounds__(128) void proj_hgemm_kernel(float* __restrict__ out) {
    int kb = blockIdx.z * (C_ / PJSPLIT);       // 192 per split, 6 k-steps
    hgemm_tile<true>(g_Yh, C_, g_Wpt, C_, out, C_,
                     blockIdx.y * HBM, blockIdx.x * HBN, kb, kb + C_ / PJSPLIT);
}

// ---------------- launch -----------------------------------------------------
extern "C" void kernel_launch(void* const* d_in, const int* in_sizes, int n_in,
                              void* d_out, int out_size) {
    const float* x    = (const float*)d_in[0];
    const float* cosp = (const float*)d_in[1];
    const float* sinp = (const float*)d_in[2];
    const float* Wq   = (const float*)d_in[3];
    const float* Wk   = (const float*)d_in[4];
    const float* Wv   = (const float*)d_in[5];
    const float* Wp   = (const float*)d_in[6];
    float* out = (float*)d_out;

    // 0) convert x + zero proj target; transpose+convert weights
    xconv_kernel<<<(T_ * C_ + 255) / 256, 256>>>(x, out);
    wtrans_kernel<<<dim3(C_ / 32, C_ / 32, 4), dim3(32, 8)>>>(Wq, Wk, Wv, Wp);
    // 1) QKV: 512 x 1536, K=768, split-K=4 -> 24x8x4 = 768 blocks
    qkv_hgemm_kernel<<<dim3(NQKV / HBN, T_ / HBM, QKSPLIT), 128>>>();
    // 2) RoPE + RMSNorm + head transpose (+ split-K reduction)
    rope_norm_kernel<<<T_, 256>>>(cosp, sinp);
    // 3) Tropical flash attention: 8 pairs x 12 heads x 3 KV-splits = 288 blocks
    attn_kernel<<<dim3(8, NH_, NSPLIT), 256>>>();
    attn_merge_kernel<<<(NH_ * T_ * 32 + 255) / 256, 256>>>();
    // 4) Projection: 512x768 @ 768x768, split-K=4 -> 12x8x4 = 384 blocks
    proj_hgemm_kernel<<<dim3(C_ / HBN, T_ / HBM, PJSPLIT), 128>>>(out);
}

// round 13
// speedup vs baseline: 1.2771x; 1.2771x over previous
#include <cuda_runtime.h>
#include <cuda_fp16.h>
#include <cuda_bf16.h>

// Shapes (compile-time)
#define T_    512
#define C_    768
#define KVC_  384
#define NH_   12
#define NKV_  6
#define HD_   64
#define HALF_ 32
#define NSPLIT 3
#define NQKV  1536        // 768 q + 384 k + 384 v output columns
#define QKSPLIT 3         // QKV GEMM split-K
#define PJSPLIT 4         // proj GEMM split-K
#define M0_   16.0f       // fixed softmax max: scores provably in [-2, 16]

// ---------------- scratch (device globals: no allocs allowed) ----------------
__device__ __half g_xh[T_ * C_];            // x in fp16
__device__ __half g_Wqkvt[NQKV * C_];       // [n][k] fp16
__device__ __half g_Wpt[C_ * C_];           // Wproj^T [n][k] fp16
__device__ float  g_qkvp[QKSPLIT][T_ * NQKV];  // QKV split-K partials
__device__ float  g_Q[NH_ * T_ * HD_];      // head-major, rope+rmsnormed
__device__ float  g_K[NKV_ * T_ * HD_];
__device__ float  g_V[NKV_ * T_ * HD_];
__device__ __half g_Yh[T_ * C_];            // attention output fp16 (t, h*64+d)
// split-KV attention partials (fixed-max softmax: just acc and denom)
__device__ float g_Pa[NSPLIT][NH_ * T_ * HD_];
__device__ float g_Pl[NSPLIT][NH_ * T_];

// ---------------- kernel 0a: convert x to fp16 + zero proj target ------------
__global__ void xconv_kernel(const float* __restrict__ x, float* __restrict__ out) {
    int i = blockIdx.x * blockDim.x + threadIdx.x;
    if (i < T_ * C_) { g_xh[i] = __float2half(x[i]); out[i] = 0.0f; }
}

// ---------------- kernel 0b: transpose+convert weights to [n][k] fp16 --------
__global__ void wtrans_kernel(const float* __restrict__ Wq,
                              const float* __restrict__ Wk,
                              const float* __restrict__ Wv,
                              const float* __restrict__ Wp) {
    __shared__ float tile[32][33];
    const float* W; __half* dst; int ncols;
    switch (blockIdx.z) {
        case 0: W = Wq; ncols = C_;   dst = g_Wqkvt;                 break;
        case 1: W = Wk; ncols = KVC_; dst = g_Wqkvt + 768 * C_;      break;
        case 2: W = Wv; ncols = KVC_; dst = g_Wqkvt + 1152 * C_;     break;
        default: W = Wp; ncols = C_;  dst = g_Wpt;                   break;
    }
    int k0 = blockIdx.x * 32;
    int n0 = blockIdx.y * 32;
    if (n0 >= ncols) return;
    int tx = threadIdx.x, ty = threadIdx.y;
#pragma unroll
    for (int i = 0; i < 4; i++) {
        int r = ty + i * 8;
        tile[r][tx] = W[(size_t)(k0 + r) * ncols + n0 + tx];
    }
    __syncthreads();
#pragma unroll
    for (int i = 0; i < 4; i++) {
        int r = ty + i * 8;
        dst[(size_t)(n0 + r) * C_ + k0 + tx] = __float2half(tile[tx][r]);
    }
}

// ---------------- fp16 tensor-core GEMM tile (3-stage pipeline) --------------
#define HBM 64
#define HBN 64
#define HBK 32
#define HSA 40
#define NST 3

__device__ __forceinline__ void mma16816(float* d, const unsigned* a, const unsigned* b) {
    asm volatile(
        "mma.sync.aligned.m16n8k16.row.col.f32.f16.f16.f32 "
        "{%0,%1,%2,%3}, {%4,%5,%6,%7}, {%8,%9}, {%0,%1,%2,%3};"
        : "+f"(d[0]), "+f"(d[1]), "+f"(d[2]), "+f"(d[3])
        : "r"(a[0]), "r"(a[1]), "r"(a[2]), "r"(a[3]), "r"(b[0]), "r"(b[1]));
}

__device__ __forceinline__ void ldsm4(unsigned* d, const __half* p) {
    unsigned addr = (unsigned)__cvta_generic_to_shared(p);
    asm volatile("ldmatrix.sync.aligned.m8n8.x4.shared.b16 {%0,%1,%2,%3}, [%4];"
                 : "=r"(d[0]), "=r"(d[1]), "=r"(d[2]), "=r"(d[3]) : "r"(addr));
}

__device__ __forceinline__ void cpasync16(const __half* s, const __half* g) {
    unsigned addr = (unsigned)__cvta_generic_to_shared(s);
    asm volatile("cp.async.cg.shared.global [%0], [%1], 16;" :: "r"(addr), "l"(g));
}

template<bool ATOMIC>
__device__ __forceinline__ void hgemm_tile(
        const __half* __restrict__ A, int lda,
        const __half* __restrict__ Bt, int ldb,
        float* __restrict__ C, int ldc,
        int m0, int n0, int k_begin, int k_end) {
    __shared__ __align__(16) __half As[NST][HBM][HSA];
    __shared__ __align__(16) __half Bs[NST][HBN][HSA];

    const int tid = threadIdx.x;
    const int w = tid >> 5, lane = tid & 31;
    const int wm = (w >> 1) * 32, wn = (w & 1) * 32;
    const int g = lane >> 2, t = lane & 3;

    float acc[2][4][4] = {};
    const int nsteps = (k_end - k_begin) / HBK;   // >= 2 for all call sites

    auto load_stage = [&](int st, int k0) {
#pragma unroll
        for (int i = 0; i < 2; i++) {
            int c = tid + i * 128;
            int r = c >> 2, col = (c & 3) * 8;
            cpasync16(&As[st][r][col], A + (size_t)(m0 + r) * lda + k0 + col);
            cpasync16(&Bs[st][r][col], Bt + (size_t)(n0 + r) * ldb + k0 + col);
        }
    };

    load_stage(0, k_begin);
    asm volatile("cp.async.commit_group;");
    load_stage(1, k_begin + HBK);
    asm volatile("cp.async.commit_group;");

    for (int s = 0; s < nsteps; s++) {
        int st = s % NST;
        if (s + 1 < nsteps) asm volatile("cp.async.wait_group 1;");
        else                asm volatile("cp.async.wait_group 0;");
        __syncthreads();
        if (s + 2 < nsteps) {
            load_stage((s + 2) % NST, k_begin + (s + 2) * HBK);
            asm volatile("cp.async.commit_group;");
        }
#pragma unroll
        for (int ks = 0; ks < 2; ks++) {
            unsigned a[2][4], b[2][4];
#pragma unroll
            for (int mt = 0; mt < 2; mt++)
                ldsm4(a[mt], &As[st][wm + mt * 16 + (lane & 15)][ks * 16 + (lane >> 4) * 8]);
#pragma unroll
            for (int p = 0; p < 2; p++)
                ldsm4(b[p], &Bs[st][wn + p * 16 + ((lane >> 4) & 1) * 8 + (lane & 7)]
                               [ks * 16 + ((lane >> 3) & 1) * 8]);
#pragma unroll
            for (int mt = 0; mt < 2; mt++)
#pragma unroll
                for (int p = 0; p < 2; p++) {
                    mma16816(acc[mt][2 * p],     a[mt], &b[p][0]);
                    mma16816(acc[mt][2 * p + 1], a[mt], &b[p][2]);
                }
        }
    }

#pragma unroll
    for (int mt = 0; mt < 2; mt++) {
#pragma unroll
        for (int nt = 0; nt < 4; nt++) {
            int row0 = m0 + wm + mt * 16 + g;
            int col  = n0 + wn + nt * 8 + 2 * t;
            if (ATOMIC) {
                atomicAdd(&C[(size_t)row0 * ldc + col],     acc[mt][nt][0]);
                atomicAdd(&C[(size_t)row0 * ldc + col + 1], acc[mt][nt][1]);
                atomicAdd(&C[(size_t)(row0 + 8) * ldc + col],     acc[mt][nt][2]);
                atomicAdd(&C[(size_t)(row0 + 8) * ldc + col + 1], acc[mt][nt][3]);
            } else {
                *(float2*)&C[(size_t)row0 * ldc + col] = make_float2(acc[mt][nt][0], acc[mt][nt][1]);
                *(float2*)&C[(size_t)(row0 + 8) * ldc + col] = make_float2(acc[mt][nt][2], acc[mt][nt][3]);
            }
        }
    }
}

// ---------------- kernel 1: QKV GEMM (split-K=3, partial buffers) ------------
__global__ __launch_bounds__(128) void qkv_hgemm_kernel() {
    int sp = blockIdx.z;
    int kb = sp * (C_ / QKSPLIT);               // 256 per split, 8 k-steps
    hgemm_tile<false>(g_xh, C_, g_Wqkvt, C_, g_qkvp[sp], NQKV,
                      blockIdx.y * HBM, blockIdx.x * HBN, kb, kb + C_ / QKSPLIT);
}

// ---------------- kernel 2: RoPE + RMSNorm + head transpose + split-K sum ----
__global__ void rope_norm_kernel(const float* __restrict__ cosp,
                                 const float* __restrict__ sinp) {
    int t = blockIdx.x;
    int warp = threadIdx.x >> 5;
    int lane = threadIdx.x & 31;
    float c = cosp[t * HALF_ + lane];
    float s = sinp[t * HALF_ + lane];

    for (int task = warp; task < 24; task += 8) {
        int col;                            // column in the 1536-wide QKV output
        if (task < NH_)             col = task * HD_;
        else if (task < NH_ + NKV_) col = 768 + (task - NH_) * HD_;
        else                        col = 1152 + (task - NH_ - NKV_) * HD_;
        size_t off = (size_t)t * NQKV + col;
        float x1 = g_qkvp[0][off + lane] + g_qkvp[1][off + lane] + g_qkvp[2][off + lane];
        float x2 = g_qkvp[0][off + lane + HALF_] + g_qkvp[1][off + lane + HALF_]
                 + g_qkvp[2][off + lane + HALF_];

        if (task < NH_) {                   // Q head
            int h = task;
            float o1 = x1 * c - x2 * s;
            float o2 = x2 * c + x1 * s;
            float ss = o1 * o1 + o2 * o2;
#pragma unroll
            for (int o = 16; o; o >>= 1) ss += __shfl_xor_sync(0xffffffffu, ss, o);
            float r = rsqrtf(ss * (1.0f / HD_) + 1e-6f);
            float* dst = g_Q + ((size_t)h * T_ + t) * HD_;
            dst[lane] = o1 * r;
            dst[lane + HALF_] = o2 * r;
        } else if (task < NH_ + NKV_) {     // K head
            int h = task - NH_;
            float o1 = x1 * c - x2 * s;
            float o2 = x2 * c + x1 * s;
            float ss = o1 * o1 + o2 * o2;
#pragma unroll
            for (int o = 16; o; o >>= 1) ss += __shfl_xor_sync(0xffffffffu, ss, o);
            float r = rsqrtf(ss * (1.0f / HD_) + 1e-6f);
            float* dst = g_K + ((size_t)h * T_ + t) * HD_;
            dst[lane] = o1 * r;
            dst[lane + HALF_] = o2 * r;
        } else {                            // V: plain head-major copy
            int h = task - NH_ - NKV_;
            float* dst = g_V + ((size_t)h * T_ + t) * HD_;
            dst[lane] = x1;
            dst[lane + HALF_] = x2;
        }
    }
}

// ---------------- kernel 3: split-KV tropical attention, FIXED-MAX softmax ---
// q,k are RMS-normalized (sum d q^2 = 64 -> |q_d| <= 8) so every tropical
// score max_d(q_d+k_d) lies in [-2, 16]. Softmax with constant max M0_=16 is
// numerically safe: weights in [e^-18, 1]. This removes the per-tile shuffle
// max chain, running-max bookkeeping, and accumulator rescales entirely.
__global__ __launch_bounds__(256, 2) void attn_kernel() {
    __shared__ float  Qs[32][68];          // [row][d] padded
    __shared__ float4 KT4[16][33];         // [d-group][key] padded
    __shared__ float2 VsT[32][34];         // [dim-pair][key]: VsT[p][j] = (V[j][2p], V[j][2p+1])
    __shared__ float4 ws4[8][4][8];        // [warp][r][key-group] staged weights

    int h = blockIdx.y;
    int split = blockIdx.z;
    int kv = h >> 1;                       // n_rep = 2
    int tid = threadIdx.x;
    int warp = tid >> 5, lane = tid & 31;
    const float* Kb = g_K + (size_t)kv * T_ * HD_;
    const float* Vb = g_V + (size_t)kv * T_ * HD_;

    for (int pass = 0; pass < 2; pass++) {
        int qt = pass ? (15 - blockIdx.x) : blockIdx.x;
        int qbase = qt * 32;
        __syncthreads();                   // protect previous pass's shared reads
#pragma unroll
        for (int i = 0; i < 2; i++) {      // load 32x64 Q tile
            int f = tid + i * 256;
            int r = f >> 4, dg = f & 15;
            float4 qv = *(const float4*)(g_Q + ((size_t)h * T_ + qbase + r) * HD_ + dg * 4);
            *(float4*)&Qs[r][dg * 4] = qv;
        }

        float l[4], a0[4], a1[4], s[4];
#pragma unroll
        for (int r = 0; r < 4; r++) { l[r] = 0.0f; a0[r] = 0.0f; a1[r] = 0.0f; }
        int qi0 = qbase + warp * 4;        // warp's first q row

        for (int j0 = split * 32; j0 < qbase + 32; j0 += NSPLIT * 32) {
            __syncthreads();               // prior tile consumed / Qs stores visible
#pragma unroll
            for (int i = 0; i < 2; i++) {  // load K (transposed) + V (pair-major)
                int f = tid + i * 256;
                int j = f >> 4, dg = f & 15;
                KT4[dg][j] = *(const float4*)(Kb + (size_t)(j0 + j) * HD_ + dg * 4);
                float4 vv = *(const float4*)(Vb + (size_t)(j0 + j) * HD_ + dg * 4);
                VsT[dg * 2 + 0][j] = make_float2(vv.x, vv.y);
                VsT[dg * 2 + 1][j] = make_float2(vv.z, vv.w);
            }
            __syncthreads();
            if (j0 > qi0 + 3) continue;    // tile fully masked for this warp

            // --- scores: s[r] = max_d(q[r][d] + k[lane][d]) ---
#pragma unroll
            for (int r = 0; r < 4; r++) s[r] = -1e30f;
#pragma unroll
            for (int dg = 0; dg < 16; dg++) {
                float4 k4 = KT4[dg][lane];
#pragma unroll
                for (int r = 0; r < 4; r++) {
                    float4 q4 = *(const float4*)&Qs[warp * 4 + r][dg * 4];
                    float t0 = fmaxf(q4.x + k4.x, q4.y + k4.y);
                    float t1 = fmaxf(q4.z + k4.z, q4.w + k4.w);
                    s[r] = fmaxf(s[r], fmaxf(t0, t1));
                }
            }
            // --- fixed-max softmax weights (lane = key), no reductions ---
#pragma unroll
            for (int r = 0; r < 4; r++) {
                int qi = qi0 + r;
                float w = (j0 + lane > qi) ? 0.0f : __expf(s[r] - M0_);  // causal
                l[r] += w;                            // per-lane partial denom
                ((float*)&ws4[warp][r][0])[lane] = w;
            }
            __syncwarp();
            // --- PV: lane = dim pair (2*lane, 2*lane+1), float4 over keys ---
#pragma unroll
            for (int r = 0; r < 4; r++) {
                float acc0 = a0[r], acc1 = a1[r];
#pragma unroll
                for (int jb = 0; jb < 8; jb++) {
                    float4 w4 = ws4[warp][r][jb];                        // broadcast
                    float4 vA = *(const float4*)&VsT[lane][jb * 4];
                    float4 vB = *(const float4*)&VsT[lane][jb * 4 + 2];
                    acc0 += w4.x * vA.x; acc1 += w4.x * vA.y;
                    acc0 += w4.y * vA.z; acc1 += w4.y * vA.w;
                    acc0 += w4.z * vB.x; acc1 += w4.z * vB.y;
                    acc0 += w4.w * vB.z; acc1 += w4.w * vB.w;
                }
                a0[r] = acc0; a1[r] = acc1;
            }
        }
        // --- finalize: reduce l across lanes, write split partials ---
#pragma unroll
        for (int r = 0; r < 4; r++) {
            float ls = l[r];
#pragma unroll
            for (int o = 16; o; o >>= 1) ls += __shfl_xor_sync(0xffffffffu, ls, o);
            int idx = h * T_ + qi0 + r;
            float* Pa = &g_Pa[split][(size_t)idx * HD_];
            Pa[2 * lane]     = a0[r];
            Pa[2 * lane + 1] = a1[r];
            if (lane == 0) g_Pl[split][idx] = ls;
        }
    }
}

// ---------------- kernel 3b: merge KV-split partials (plain sum), fp16 Y -----
__global__ void attn_merge_kernel() {
    int gw = (blockIdx.x * blockDim.x + threadIdx.x) >> 5;
    int lane = threadIdx.x & 31;
    if (gw >= NH_ * T_) return;
    int h = gw / T_, qi = gw % T_;
    float l = 0.0f;
#pragma unroll
    for (int sp = 0; sp < NSPLIT; sp++) l += g_Pl[sp][gw];
    float inv = 1.0f / l;
    float y0 = 0.0f, y1 = 0.0f;
#pragma unroll
    for (int sp = 0; sp < NSPLIT; sp++) {
        const float* A = &g_Pa[sp][(size_t)gw * HD_];
        y0 += A[lane];
        y1 += A[lane + HALF_];
    }
    __half* Yp = g_Yh + (size_t)qi * C_ + h * HD_;
    Yp[lane] = __float2half(y0 * inv);
    Yp[lane + HALF_] = __float2half(y1 * inv);
}

// ---------------- kernel 4: output projection (split-K=4, atomics) -----------
__global__ __launch_bounds__(128) void proj_hgemm_kernel(float* __restrict__ out) {
    int kb = blockIdx.z * (C_ / PJSPLIT);       // 192 per split, 6 k-steps
    hgemm_tile<true>(g_Yh, C_, g_Wpt, C_, out, C_,
                     blockIdx.y * HBM, blockIdx.x * HBN, kb, kb + C_ / PJSPLIT);
}

// ---------------- launch -----------------------------------------------------
extern "C" void kernel_launch(void* const* d_in, const int* in_sizes, int n_in,
                              void* d_out, int out_size) {
    const float* x    = (const float*)d_in[0];
    const float* cosp = (const float*)d_in[1];
    const float* sinp = (const float*)d_in[2];
    const float* Wq   = (const float*)d_in[3];
    const float* Wk   = (const float*)d_in[4];
    const float* Wv   = (const float*)d_in[5];
    const float* Wp   = (const float*)d_in[6];
    float* out = (float*)d_out;

    // 0) convert x + zero proj target; transpose+convert weights
    xconv_kernel<<<(T_ * C_ + 255) / 256, 256>>>(x, out);
    wtrans_kernel<<<dim3(C_ / 32, C_ / 32, 4), dim3(32, 8)>>>(Wq, Wk, Wv, Wp);
    // 1) QKV: 512 x 1536, K=768, split-K=3 -> 576 blocks
    qkv_hgemm_kernel<<<dim3(NQKV / HBN, T_ / HBM, QKSPLIT), 128>>>();
    // 2) RoPE + RMSNorm + head transpose (+ split-K reduction)
    rope_norm_kernel<<<T_, 256>>>(cosp, sinp);
    // 3) Tropical flash attention: 8 pairs x 12 heads x 3 KV-splits = 288 blocks
    attn_kernel<<<dim3(8, NH_, NSPLIT), 256>>>();
    attn_merge_kernel<<<(NH_ * T_ * 32 + 255) / 256, 256>>>();
    // 4) Projection: 512x768 @ 768x768, split-K=4 -> 384 blocks
    proj_hgemm_kernel<<<dim3(C_ / HBN, T_ / HBM, PJSPLIT), 128>>>(out);
}